// round 2
// baseline (speedup 1.0000x reference)
#include <cuda_runtime.h>

// Quanvolution via closed-form expectation values (Heisenberg picture):
//   a0 = x0 + w0, a1 = x1 + w1
//   <Z0> = cos(w2) * cos(a0)
//   <Z1> = cos(a1)
//   <Z2> = cos(a0) * cos(x2)
//   <Z3> = cos(w3) * cos(a0) * cos(x2) * cos(x3)
//
// Input  x: [32, 1, 512, 512] fp32
// Output  : [32, 4, 256, 256] fp32
//
// Each thread: 4 adjacent patches. Reads 2x float4 from row 2j and 2x float4
// from row 2j+1 (64B, MLP=4), writes one float4 per output plane (4x 16B).

#define HP      256
#define WP      256
#define PLANE   (HP * WP)                         // 65536
#define NTHREADS_TOTAL (32 * HP * (WP / 4))       // 524,288

__global__ __launch_bounds__(256)
void quanv_kernel(const float* __restrict__ x,
                  const float* __restrict__ w,
                  float* __restrict__ out) {
    int idx = blockIdx.x * blockDim.x + threadIdx.x;   // [0, 524288)
    int kk = idx & 63;             // group of 4 patches (8 input columns)
    int j  = (idx >> 6) & 255;     // patch row
    int b  = idx >> 14;            // batch

    const float w0  = __ldg(w + 0);
    const float w1  = __ldg(w + 1);
    const float cw2 = __cosf(__ldg(w + 2));
    const float cw3 = __cosf(__ldg(w + 3));

    // input rows 2j, 2j+1; columns [8*kk, 8*kk+8)
    const float4* row0 = reinterpret_cast<const float4*>(
        x + ((size_t)b * 512 + 2 * (size_t)j) * 512) + 2 * kk;
    const float4* row1 = row0 + 128;   // +512 floats = next row

    float4 r0a = __ldcs(row0);
    float4 r0b = __ldcs(row0 + 1);
    float4 r1a = __ldcs(row1);
    float4 r1b = __ldcs(row1 + 1);

    // patch 0: (r0a.x, r0a.y, r1a.x, r1a.y)
    // patch 1: (r0a.z, r0a.w, r1a.z, r1a.w)
    // patch 2: (r0b.x, r0b.y, r1b.x, r1b.y)
    // patch 3: (r0b.z, r0b.w, r1b.z, r1b.w)
    float c0_0 = __cosf(r0a.x + w0);
    float c0_1 = __cosf(r0a.z + w0);
    float c0_2 = __cosf(r0b.x + w0);
    float c0_3 = __cosf(r0b.z + w0);

    float c1_0 = __cosf(r0a.y + w1);
    float c1_1 = __cosf(r0a.w + w1);
    float c1_2 = __cosf(r0b.y + w1);
    float c1_3 = __cosf(r0b.w + w1);

    float x2_0 = __cosf(r1a.x);
    float x2_1 = __cosf(r1a.z);
    float x2_2 = __cosf(r1b.x);
    float x2_3 = __cosf(r1b.z);

    float x3_0 = __cosf(r1a.y);
    float x3_1 = __cosf(r1a.w);
    float x3_2 = __cosf(r1b.y);
    float x3_3 = __cosf(r1b.w);

    float e2_0 = c0_0 * x2_0;
    float e2_1 = c0_1 * x2_1;
    float e2_2 = c0_2 * x2_2;
    float e2_3 = c0_3 * x2_3;

    float* o = out + (((size_t)b * 4) * HP + j) * WP + 4 * (size_t)kk;

    __stcs(reinterpret_cast<float4*>(o),
           make_float4(cw2 * c0_0, cw2 * c0_1, cw2 * c0_2, cw2 * c0_3));
    __stcs(reinterpret_cast<float4*>(o + PLANE),
           make_float4(c1_0, c1_1, c1_2, c1_3));
    __stcs(reinterpret_cast<float4*>(o + 2 * PLANE),
           make_float4(e2_0, e2_1, e2_2, e2_3));
    __stcs(reinterpret_cast<float4*>(o + 3 * PLANE),
           make_float4(cw3 * e2_0 * x3_0, cw3 * e2_1 * x3_1,
                       cw3 * e2_2 * x3_2, cw3 * e2_3 * x3_3));
}

extern "C" void kernel_launch(void* const* d_in, const int* in_sizes, int n_in,
                              void* d_out, int out_size) {
    const float* x = (const float*)d_in[0];
    const float* w = (const float*)d_in[1];
    float* out = (float*)d_out;

    dim3 block(256);
    dim3 grid(NTHREADS_TOTAL / 256);   // 2048 blocks
    quanv_kernel<<<grid, block>>>(x, w, out);
}

// round 3
// speedup vs baseline: 1.1269x; 1.1269x over previous
#include <cuda_runtime.h>

// Quanvolution via closed-form expectation values (Heisenberg picture):
//   a0 = x0 + w0, a1 = x1 + w1
//   <Z0> = cos(w2)*cos(a0); <Z1> = cos(a1); <Z2> = cos(a0)*cos(x2)
//   <Z3> = cos(w3)*cos(a0)*cos(x2)*cos(x3)
//
// Input  x: [32,1,512,512] fp32 -> Output [32,4,256,256] fp32
//
// Persistent single-wave grid (148 SMs x 7 CTAs), depth-2 software pipeline:
// each work item = 2 horizontal patches (one float4 from each of 2 rows,
// one float2 store into each of 4 output planes).

#define HP      256
#define WP      256
#define PLANE   (HP * WP)                 // 65536
#define NTILES  (32 * HP * (WP / 2))      // 1,048,576 work items
#define NCTAS   1036                      // 148 SMs * 7
#define NTHREADS (NCTAS * 256)            // 265,216

__global__ __launch_bounds__(256, 7)
void quanv_kernel(const float* __restrict__ x,
                  const float* __restrict__ w,
                  float* __restrict__ out) {
    const int stride = NTHREADS;
    int i = blockIdx.x * blockDim.x + threadIdx.x;
    if (i >= NTILES) return;   // never taken, keeps loop well-formed

    const float w0  = __ldg(w + 0);
    const float w1  = __ldg(w + 1);
    const float cw2 = __cosf(__ldg(w + 2));
    const float cw3 = __cosf(__ldg(w + 3));

    // ---- pipeline stage 0: load for first work item ----
    int kk = i & 127;
    int j  = (i >> 7) & 255;
    int b  = i >> 15;
    const float4* p0 = reinterpret_cast<const float4*>(
        x + ((size_t)b * 512 + 2 * (size_t)j) * 512) + kk;
    float4 r0 = __ldg(p0);
    float4 r1 = __ldg(p0 + 128);
    size_t obase = (((size_t)b * 4) * HP + j) * WP + 2 * (size_t)kk;

    #pragma unroll 1
    while (true) {
        // ---- prefetch next work item ----
        int ni = i + stride;
        bool more = ni < NTILES;
        float4 n0, n1;
        size_t nobase = 0;
        if (more) {
            int nkk = ni & 127;
            int nj  = (ni >> 7) & 255;
            int nb  = ni >> 15;
            const float4* np = reinterpret_cast<const float4*>(
                x + ((size_t)nb * 512 + 2 * (size_t)nj) * 512) + nkk;
            n0 = __ldg(np);
            n1 = __ldg(np + 128);
            nobase = (((size_t)nb * 4) * HP + nj) * WP + 2 * (size_t)nkk;
        }

        // ---- compute + store current ----
        // patch A: (r0.x, r0.y, r1.x, r1.y); patch B: (r0.z, r0.w, r1.z, r1.w)
        float c0a = __cosf(r0.x + w0);
        float c1a = __cosf(r0.y + w1);
        float c2a = __cosf(r1.x);
        float c3a = __cosf(r1.y);

        float c0b = __cosf(r0.z + w0);
        float c1b = __cosf(r0.w + w1);
        float c2b = __cosf(r1.z);
        float c3b = __cosf(r1.w);

        float e2a = c0a * c2a;
        float e2b = c0b * c2b;

        float* o = out + obase;
        *reinterpret_cast<float2*>(o)             = make_float2(cw2 * c0a, cw2 * c0b);
        *reinterpret_cast<float2*>(o + PLANE)     = make_float2(c1a,        c1b);
        *reinterpret_cast<float2*>(o + 2 * PLANE) = make_float2(e2a,        e2b);
        *reinterpret_cast<float2*>(o + 3 * PLANE) = make_float2(cw3 * e2a * c3a,
                                                                cw3 * e2b * c3b);

        if (!more) break;
        i = ni;
        r0 = n0;
        r1 = n1;
        obase = nobase;
    }
}

extern "C" void kernel_launch(void* const* d_in, const int* in_sizes, int n_in,
                              void* d_out, int out_size) {
    const float* x = (const float*)d_in[0];
    const float* w = (const float*)d_in[1];
    float* out = (float*)d_out;

    quanv_kernel<<<NCTAS, 256>>>(x, w, out);
}